// round 8
// baseline (speedup 1.0000x reference)
#include <cuda_runtime.h>
#include <cstdint>

// Problem constants (fixed by setup_inputs)
#define B_    16
#define CIN   64
#define COUT  64
#define H_    224
#define W_    224
#define PH    32
#define PW    32

#define THREADS 256
#define CO_PB 8
#define CONV_BLOCKS (B_ * (COUT / CO_PB) * 2)   // 256
#define COPY_BLOCKS (B_ * COUT)                 // 1024: one CTA per (b,c) image
#define IMG_BYTES (H_ * W_ * 4)                 // 200704
#define ROW_BYTES (W_ * 4)                      // 896
#define ROW_F4 56

#define ROWS_IN 18
#define ROW_S  36
#define IN_SMEM (8 * ROWS_IN * ROW_S)           // 5184 floats
#define W_SMEM  (8 * 8 * 9)                     // 576 floats

#define CHUNK 24320                             // bulk-copy chunk bytes (16B mult)
#define SMEM_BYTES (2 * CHUNK + 64)             // 48704 <= 48KB static limit

__device__ __forceinline__ uint32_t smem_u32(const void* p) {
    uint32_t a;
    asm("{ .reg .u64 t; cvta.to.shared.u64 t, %1; cvt.u32.u64 %0, t; }"
        : "=r"(a) : "l"(p));
    return a;
}

__device__ __forceinline__ void mbar_wait(uint32_t mb, uint32_t parity) {
    asm volatile(
        "{\n\t.reg .pred P;\n\t"
        "L1_%=:\n\t"
        "mbarrier.try_wait.parity.shared.b64 P, [%0], %1, 0x989680;\n\t"
        "@P bra.uni L2_%=;\n\t"
        "bra.uni L1_%=;\n\t"
        "L2_%=:\n\t}"
        :: "r"(mb), "r"(parity) : "memory");
}

__device__ __forceinline__ void store_row_patch(float4* __restrict__ d, int q,
                                                float4 v, int x0)
{
    int xlo = q * 4;
    if (xlo + 3 < x0 || xlo >= x0 + PW) {
        d[q] = v;                                // fully outside patch-x
    } else if (xlo >= x0 && xlo + 3 < x0 + PW) {
        // fully inside: conv block owns it
    } else {
        float vv[4] = {v.x, v.y, v.z, v.w};
        #pragma unroll
        for (int k = 0; k < 4; k++) {
            int x = xlo + k;
            if (x < x0 || x >= x0 + PW) ((float*)d)[xlo + k] = vv[k];
        }
    }
}

__global__ __launch_bounds__(THREADS, 4)
void inc_conv_fused(const float* __restrict__ in,
                    const float* __restrict__ wgt,
                    const float* __restrict__ bias,
                    const float* __restrict__ prev,
                    const int*   __restrict__ loc,
                    float* __restrict__ out)
{
    __shared__ __align__(128) unsigned char smem_raw[SMEM_BYTES];
    const int tid = threadIdx.x;
    const int bid = blockIdx.x;

    if (bid < CONV_BLOCKS) {
        // ------------- conv path: block = (batch, 8 Cout, 16-row half) -------------
        float* smem = (float*)smem_raw;
        float (*in_s)[ROWS_IN][ROW_S] = (float (*)[ROWS_IN][ROW_S])smem;
        float* w_s = smem + IN_SMEM;

        const int b   = bid >> 4;
        const int rem = bid & 15;
        const int cob = (rem >> 1) * CO_PB;
        const int ys  = (rem & 1) * 16;
        const int y0  = loc[2 * b];
        const int x0  = loc[2 * b + 1];

        float acc[CO_PB][2];
        #pragma unroll
        for (int co = 0; co < CO_PB; co++) { acc[co][0] = 0.f; acc[co][1] = 0.f; }

        const int oyb = tid >> 5;
        const int ox  = tid & 31;

        for (int ci0 = 0; ci0 < CIN; ci0 += 8) {
            __syncthreads();
            for (int i = tid; i < 8 * ROWS_IN * 34; i += THREADS) {
                int ci = i / (ROWS_IN * 34);
                int rr = i % (ROWS_IN * 34);
                int r = rr / 34, c = rr % 34;
                int iy = y0 - 1 + ys + r;
                int ix = x0 - 1 + c;
                float v = 0.f;
                if (iy >= 0 && ix >= 0)
                    v = in[(((b * CIN) + ci0 + ci) * H_ + iy) * W_ + ix];
                in_s[ci][r][c] = v;
            }
            for (int i = tid; i < W_SMEM; i += THREADS) {
                int co = i & 7;
                int k  = (i >> 3) % 9;
                int ci = i / 72;
                w_s[(ci * 9 + k) * 8 + co] =
                    wgt[((cob + co) * CIN + ci0 + ci) * 9 + k];
            }
            __syncthreads();

            #pragma unroll
            for (int ci = 0; ci < 8; ci++) {
                #pragma unroll
                for (int kh = 0; kh < 3; kh++) {
                    float i0[3], i1[3];
                    #pragma unroll
                    for (int kw = 0; kw < 3; kw++) {
                        i0[kw] = in_s[ci][oyb + kh][ox + kw];
                        i1[kw] = in_s[ci][oyb + 8 + kh][ox + kw];
                    }
                    #pragma unroll
                    for (int kw = 0; kw < 3; kw++) {
                        const float4 wA = *(const float4*)&w_s[(ci * 9 + kh * 3 + kw) * 8];
                        const float4 wB = *(const float4*)&w_s[(ci * 9 + kh * 3 + kw) * 8 + 4];
                        float wv[8] = {wA.x, wA.y, wA.z, wA.w, wB.x, wB.y, wB.z, wB.w};
                        #pragma unroll
                        for (int co = 0; co < CO_PB; co++) {
                            acc[co][0] = fmaf(i0[kw], wv[co], acc[co][0]);
                            acc[co][1] = fmaf(i1[kw], wv[co], acc[co][1]);
                        }
                    }
                }
            }
        }

        #pragma unroll
        for (int co = 0; co < CO_PB; co++) {
            float bv = bias[cob + co];
            #pragma unroll
            for (int p = 0; p < 2; p++) {
                int oy = ys + oyb + 8 * p;
                out[((b * COUT + cob + co) * H_ + (y0 + oy)) * W_ + (x0 + ox)] =
                    acc[co][p] + bv;
            }
        }
    } else {
        // ------------- copy path: one CTA per image, TMA bulk pipeline -------------
        const int img = bid - CONV_BLOCKS;
        const int b   = img >> 6;
        const int y0  = loc[2 * b];
        const int x0  = loc[2 * b + 1];

        const char* srcBase = (const char*)prev + (size_t)img * IMG_BYTES;
        char*       dstBase = (char*)out  + (size_t)img * IMG_BYTES;

        if (tid == 0) {
            // --- non-patch rows via double-buffered cp.async.bulk G->S->G ---
            const int p_bytes = y0 * ROW_BYTES;                 // prefix
            const int s_off   = (y0 + PH) * ROW_BYTES;          // suffix start
            const int s_bytes = IMG_BYTES - s_off;
            const int ncp = (p_bytes + CHUNK - 1) / CHUNK;
            const int ncs = (s_bytes + CHUNK - 1) / CHUNK;
            const int nc  = ncp + ncs;

            uint32_t buf[2];
            buf[0] = smem_u32(smem_raw);
            buf[1] = buf[0] + CHUNK;
            uint32_t mb[2];
            mb[0] = buf[0] + 2 * CHUNK;
            mb[1] = mb[0] + 8;
            asm volatile("mbarrier.init.shared.b64 [%0], 1;" :: "r"(mb[0]) : "memory");
            asm volatile("mbarrier.init.shared.b64 [%0], 1;" :: "r"(mb[1]) : "memory");
            asm volatile("fence.proxy.async.shared::cta;" ::: "memory");

            // chunk k -> (src, dst, size)
            auto chunk_of = [&](int k, const char*& s, char*& d, int& sz) {
                if (k < ncp) {
                    int off = k * CHUNK;
                    sz = min(CHUNK, p_bytes - off);
                    s = srcBase + off; d = dstBase + off;
                } else {
                    int off = (k - ncp) * CHUNK;
                    sz = min(CHUNK, s_bytes - off);
                    s = srcBase + s_off + off; d = dstBase + s_off + off;
                }
            };
            auto issue_gs = [&](int k) {
                const char* s; char* d; int sz;
                chunk_of(k, s, d, sz);
                int j = k & 1;
                asm volatile("mbarrier.arrive.expect_tx.shared.b64 _, [%0], %1;"
                             :: "r"(mb[j]), "r"((uint32_t)sz) : "memory");
                asm volatile("cp.async.bulk.shared::cta.global.mbarrier::complete_tx::bytes "
                             "[%0], [%1], %2, [%3];"
                             :: "r"(buf[j]), "l"(s), "r"((uint32_t)sz), "r"(mb[j])
                             : "memory");
            };

            if (nc > 0) issue_gs(0);
            if (nc > 1) issue_gs(1);
            for (int k = 0; k < nc; k++) {
                int j = k & 1;
                mbar_wait(mb[j], (uint32_t)((k >> 1) & 1));
                const char* s; char* d; int sz;
                chunk_of(k, s, d, sz);
                asm volatile("cp.async.bulk.global.shared::cta.bulk_group [%0], [%1], %2;"
                             :: "l"(d), "r"(buf[j]), "r"((uint32_t)sz) : "memory");
                asm volatile("cp.async.bulk.commit_group;" ::: "memory");
                if (k + 2 < nc) {
                    // buffer j reusable once its smem reads drained
                    asm volatile("cp.async.bulk.wait_group.read 0;" ::: "memory");
                    issue_gs(k + 2);
                }
            }
            asm volatile("cp.async.bulk.wait_group 0;" ::: "memory");
        } else if (tid >= 32) {
            // --- 32 patch rows via float4 with x-skip (overlaps TMA pipeline) ---
            const int t = tid - 32;                      // 0..223
            const float4* srcf = (const float4*)srcBase;
            float4* dstf = (float4*)dstBase;
            const int base = y0 * ROW_F4;
            #pragma unroll
            for (int k = 0; k < 8; k++) {
                int idx = t + 224 * k;                   // 0..1791
                int r = idx / ROW_F4;
                int q = idx % ROW_F4;
                float4 v = srcf[base + idx];
                store_row_patch(dstf + (size_t)(y0 + r) * ROW_F4, q, v, x0);
            }
        }
    }
}

extern "C" void kernel_launch(void* const* d_in, const int* in_sizes, int n_in,
                              void* d_out, int out_size) {
    const float* in   = (const float*)d_in[0];
    const float* wgt  = (const float*)d_in[1];
    const float* bias = (const float*)d_in[2];
    const float* prev = (const float*)d_in[3];
    const int*   loc  = (const int*)d_in[4];
    float* out = (float*)d_out;

    inc_conv_fused<<<CONV_BLOCKS + COPY_BLOCKS, THREADS>>>(in, wgt, bias, prev, loc, out);
}

// round 9
// speedup vs baseline: 1.0006x; 1.0006x over previous
#include <cuda_runtime.h>
#include <cstdint>

// Problem constants (fixed by setup_inputs)
#define B_    16
#define CIN   64
#define COUT  64
#define H_    224
#define W_    224
#define PH    32
#define PW    32

#define THREADS 256
#define CO_PB 8
#define CONV_BLOCKS (B_ * (COUT / CO_PB) * 2)   // 256
#define COPY_BLOCKS (B_ * COUT)                 // 1024: one CTA per (b,c) image
#define IMG_BYTES (H_ * W_ * 4)                 // 200704
#define ROW_BYTES (W_ * 4)                      // 896
#define ROW_F4 56

#define ROWS_IN 18
#define ROW_S  36
#define IN_SMEM (8 * ROWS_IN * ROW_S)           // 5184 floats
#define W_SMEM  (8 * 8 * 9)                     // 576 floats

#define CHUNK 24320                             // bulk-copy chunk bytes (16B mult)
#define SMEM_BYTES (2 * CHUNK + 64)             // 48704 <= 48KB static limit

__device__ __forceinline__ uint32_t smem_u32(const void* p) {
    uint32_t a;
    asm("{ .reg .u64 t; cvta.to.shared.u64 t, %1; cvt.u32.u64 %0, t; }"
        : "=r"(a) : "l"(p));
    return a;
}

__device__ __forceinline__ void mbar_wait(uint32_t mb, uint32_t parity) {
    asm volatile(
        "{\n\t.reg .pred P;\n\t"
        "L1_%=:\n\t"
        "mbarrier.try_wait.parity.shared.b64 P, [%0], %1, 0x989680;\n\t"
        "@P bra.uni L2_%=;\n\t"
        "bra.uni L1_%=;\n\t"
        "L2_%=:\n\t}"
        :: "r"(mb), "r"(parity) : "memory");
}

__device__ __forceinline__ void store_row_patch(float4* __restrict__ d, int q,
                                                float4 v, int x0)
{
    int xlo = q * 4;
    if (xlo + 3 < x0 || xlo >= x0 + PW) {
        d[q] = v;                                // fully outside patch-x
    } else if (xlo >= x0 && xlo + 3 < x0 + PW) {
        // fully inside: conv block owns it
    } else {
        float vv[4] = {v.x, v.y, v.z, v.w};
        #pragma unroll
        for (int k = 0; k < 4; k++) {
            int x = xlo + k;
            if (x < x0 || x >= x0 + PW) ((float*)d)[xlo + k] = vv[k];
        }
    }
}

__global__ __launch_bounds__(THREADS, 4)
void inc_conv_fused(const float* __restrict__ in,
                    const float* __restrict__ wgt,
                    const float* __restrict__ bias,
                    const float* __restrict__ prev,
                    const int*   __restrict__ loc,
                    float* __restrict__ out)
{
    __shared__ __align__(128) unsigned char smem_raw[SMEM_BYTES];
    const int tid = threadIdx.x;
    const int bid = blockIdx.x;

    if (bid < CONV_BLOCKS) {
        // ------------- conv path: block = (batch, 8 Cout, 16-row half) -------------
        float* smem = (float*)smem_raw;
        float (*in_s)[ROWS_IN][ROW_S] = (float (*)[ROWS_IN][ROW_S])smem;
        float* w_s = smem + IN_SMEM;

        const int b   = bid >> 4;
        const int rem = bid & 15;
        const int cob = (rem >> 1) * CO_PB;
        const int ys  = (rem & 1) * 16;
        const int y0  = loc[2 * b];
        const int x0  = loc[2 * b + 1];

        float acc[CO_PB][2];
        #pragma unroll
        for (int co = 0; co < CO_PB; co++) { acc[co][0] = 0.f; acc[co][1] = 0.f; }

        const int oyb = tid >> 5;
        const int ox  = tid & 31;

        for (int ci0 = 0; ci0 < CIN; ci0 += 8) {
            __syncthreads();
            for (int i = tid; i < 8 * ROWS_IN * 34; i += THREADS) {
                int ci = i / (ROWS_IN * 34);
                int rr = i % (ROWS_IN * 34);
                int r = rr / 34, c = rr % 34;
                int iy = y0 - 1 + ys + r;
                int ix = x0 - 1 + c;
                float v = 0.f;
                if (iy >= 0 && ix >= 0)
                    v = in[(((b * CIN) + ci0 + ci) * H_ + iy) * W_ + ix];
                in_s[ci][r][c] = v;
            }
            for (int i = tid; i < W_SMEM; i += THREADS) {
                int co = i & 7;
                int k  = (i >> 3) % 9;
                int ci = i / 72;
                w_s[(ci * 9 + k) * 8 + co] =
                    wgt[((cob + co) * CIN + ci0 + ci) * 9 + k];
            }
            __syncthreads();

            #pragma unroll
            for (int ci = 0; ci < 8; ci++) {
                #pragma unroll
                for (int kh = 0; kh < 3; kh++) {
                    float i0[3], i1[3];
                    #pragma unroll
                    for (int kw = 0; kw < 3; kw++) {
                        i0[kw] = in_s[ci][oyb + kh][ox + kw];
                        i1[kw] = in_s[ci][oyb + 8 + kh][ox + kw];
                    }
                    #pragma unroll
                    for (int kw = 0; kw < 3; kw++) {
                        const float4 wA = *(const float4*)&w_s[(ci * 9 + kh * 3 + kw) * 8];
                        const float4 wB = *(const float4*)&w_s[(ci * 9 + kh * 3 + kw) * 8 + 4];
                        float wv[8] = {wA.x, wA.y, wA.z, wA.w, wB.x, wB.y, wB.z, wB.w};
                        #pragma unroll
                        for (int co = 0; co < CO_PB; co++) {
                            acc[co][0] = fmaf(i0[kw], wv[co], acc[co][0]);
                            acc[co][1] = fmaf(i1[kw], wv[co], acc[co][1]);
                        }
                    }
                }
            }
        }

        #pragma unroll
        for (int co = 0; co < CO_PB; co++) {
            float bv = bias[cob + co];
            #pragma unroll
            for (int p = 0; p < 2; p++) {
                int oy = ys + oyb + 8 * p;
                out[((b * COUT + cob + co) * H_ + (y0 + oy)) * W_ + (x0 + ox)] =
                    acc[co][p] + bv;
            }
        }
    } else {
        // ------------- copy path: one CTA per image, TMA bulk pipeline -------------
        const int img = bid - CONV_BLOCKS;
        const int b   = img >> 6;
        const int y0  = loc[2 * b];
        const int x0  = loc[2 * b + 1];

        const char* srcBase = (const char*)prev + (size_t)img * IMG_BYTES;
        char*       dstBase = (char*)out  + (size_t)img * IMG_BYTES;

        if (tid == 0) {
            // --- non-patch rows via double-buffered cp.async.bulk G->S->G ---
            const int p_bytes = y0 * ROW_BYTES;                 // prefix
            const int s_off   = (y0 + PH) * ROW_BYTES;          // suffix start
            const int s_bytes = IMG_BYTES - s_off;
            const int ncp = (p_bytes + CHUNK - 1) / CHUNK;
            const int ncs = (s_bytes + CHUNK - 1) / CHUNK;
            const int nc  = ncp + ncs;

            uint32_t buf[2];
            buf[0] = smem_u32(smem_raw);
            buf[1] = buf[0] + CHUNK;
            uint32_t mb[2];
            mb[0] = buf[0] + 2 * CHUNK;
            mb[1] = mb[0] + 8;
            asm volatile("mbarrier.init.shared.b64 [%0], 1;" :: "r"(mb[0]) : "memory");
            asm volatile("mbarrier.init.shared.b64 [%0], 1;" :: "r"(mb[1]) : "memory");
            asm volatile("fence.proxy.async.shared::cta;" ::: "memory");

            // chunk k -> (src, dst, size)
            auto chunk_of = [&](int k, const char*& s, char*& d, int& sz) {
                if (k < ncp) {
                    int off = k * CHUNK;
                    sz = min(CHUNK, p_bytes - off);
                    s = srcBase + off; d = dstBase + off;
                } else {
                    int off = (k - ncp) * CHUNK;
                    sz = min(CHUNK, s_bytes - off);
                    s = srcBase + s_off + off; d = dstBase + s_off + off;
                }
            };
            auto issue_gs = [&](int k) {
                const char* s; char* d; int sz;
                chunk_of(k, s, d, sz);
                int j = k & 1;
                asm volatile("mbarrier.arrive.expect_tx.shared.b64 _, [%0], %1;"
                             :: "r"(mb[j]), "r"((uint32_t)sz) : "memory");
                asm volatile("cp.async.bulk.shared::cta.global.mbarrier::complete_tx::bytes "
                             "[%0], [%1], %2, [%3];"
                             :: "r"(buf[j]), "l"(s), "r"((uint32_t)sz), "r"(mb[j])
                             : "memory");
            };

            if (nc > 0) issue_gs(0);
            if (nc > 1) issue_gs(1);
            for (int k = 0; k < nc; k++) {
                int j = k & 1;
                mbar_wait(mb[j], (uint32_t)((k >> 1) & 1));
                const char* s; char* d; int sz;
                chunk_of(k, s, d, sz);
                asm volatile("cp.async.bulk.global.shared::cta.bulk_group [%0], [%1], %2;"
                             :: "l"(d), "r"(buf[j]), "r"((uint32_t)sz) : "memory");
                asm volatile("cp.async.bulk.commit_group;" ::: "memory");
                if (k + 2 < nc) {
                    // buffer j reusable once its smem reads drained
                    asm volatile("cp.async.bulk.wait_group.read 0;" ::: "memory");
                    issue_gs(k + 2);
                }
            }
            asm volatile("cp.async.bulk.wait_group 0;" ::: "memory");
        } else if (tid >= 32) {
            // --- 32 patch rows via float4 with x-skip (overlaps TMA pipeline) ---
            const int t = tid - 32;                      // 0..223
            const float4* srcf = (const float4*)srcBase;
            float4* dstf = (float4*)dstBase;
            const int base = y0 * ROW_F4;
            #pragma unroll
            for (int k = 0; k < 8; k++) {
                int idx = t + 224 * k;                   // 0..1791
                int r = idx / ROW_F4;
                int q = idx % ROW_F4;
                float4 v = srcf[base + idx];
                store_row_patch(dstf + (size_t)(y0 + r) * ROW_F4, q, v, x0);
            }
        }
    }
}

extern "C" void kernel_launch(void* const* d_in, const int* in_sizes, int n_in,
                              void* d_out, int out_size) {
    const float* in   = (const float*)d_in[0];
    const float* wgt  = (const float*)d_in[1];
    const float* bias = (const float*)d_in[2];
    const float* prev = (const float*)d_in[3];
    const int*   loc  = (const int*)d_in[4];
    float* out = (float*)d_out;

    inc_conv_fused<<<CONV_BLOCKS + COPY_BLOCKS, THREADS>>>(in, wgt, bias, prev, loc, out);
}